// round 7
// baseline (speedup 1.0000x reference)
#include <cuda_runtime.h>
#include <cuda_bf16.h>
#include <cstdint>

#define N_NODES 50000
#define N_EDGES_MAX 800000
#define IN_DIM  256
#define OUT_DIM 256
#define M_PAD   50048          // 391 * 128

// ---------------------------------------------------------------------------
// Device-global scratch (allocation-free).
// ---------------------------------------------------------------------------
__device__ int g_deg[N_NODES];
__device__ int g_off[N_NODES + 1];
__device__ int g_cur[N_NODES];
__device__ int g_esrc[N_EDGES_MAX];
// bf16 split planes of the aggregated features (A) and transposed weight (B)
__device__ __align__(16) __nv_bfloat16 g_hiA[(size_t)M_PAD * IN_DIM];
__device__ __align__(16) __nv_bfloat16 g_loA[(size_t)M_PAD * IN_DIM];
__device__ __align__(16) __nv_bfloat16 g_hiB[(size_t)OUT_DIM * IN_DIM];  // [n][k]
__device__ __align__(16) __nv_bfloat16 g_loB[(size_t)OUT_DIM * IN_DIM];  // [n][k]

// ---------------------------------------------------------------------------
// helpers
// ---------------------------------------------------------------------------
__device__ __forceinline__ uint32_t smem_to_u32(const void* p) {
    uint32_t a;
    asm("{ .reg .u64 t; cvta.to.shared.u64 t, %1; cvt.u32.u64 %0, t; }"
        : "=r"(a) : "l"(p));
    return a;
}
__device__ __forceinline__ void ldm4(uint32_t* r, uint32_t addr) {
    asm volatile("ldmatrix.sync.aligned.m8n8.x4.shared.b16 {%0,%1,%2,%3}, [%4];"
                 : "=r"(r[0]), "=r"(r[1]), "=r"(r[2]), "=r"(r[3]) : "r"(addr));
}
__device__ __forceinline__ void mma16816(float* c, const uint32_t* a,
                                         uint32_t b0, uint32_t b1) {
    asm volatile(
        "mma.sync.aligned.m16n8k16.row.col.f32.bf16.bf16.f32 "
        "{%0,%1,%2,%3}, {%4,%5,%6,%7}, {%8,%9}, {%0,%1,%2,%3};"
        : "+f"(c[0]), "+f"(c[1]), "+f"(c[2]), "+f"(c[3])
        : "r"(a[0]), "r"(a[1]), "r"(a[2]), "r"(a[3]), "r"(b0), "r"(b1));
}
__device__ __forceinline__ void cp16(uint32_t saddr, const void* gptr) {
    asm volatile("cp.async.cg.shared.global [%0], [%1], 16;"
                 :: "r"(saddr), "l"(gptr) : "memory");
}
#define CP_COMMIT() asm volatile("cp.async.commit_group;" ::: "memory")
#define CP_WAIT(n)  asm volatile("cp.async.wait_group %0;" :: "n"(n) : "memory")

// ---------------------------------------------------------------------------
// Kernel 1: zero degree histogram
// ---------------------------------------------------------------------------
__global__ void zero_deg_kernel() {
    int i = blockIdx.x * blockDim.x + threadIdx.x;
    if (i < N_NODES) g_deg[i] = 0;
}

// ---------------------------------------------------------------------------
// Kernel 2: degree histogram over dst
// ---------------------------------------------------------------------------
__global__ void hist_kernel(const int* __restrict__ dst, int n_edges) {
    int e = blockIdx.x * blockDim.x + threadIdx.x;
    if (e < n_edges) atomicAdd(&g_deg[dst[e]], 1);
}

// ---------------------------------------------------------------------------
// Kernel 3: single-block exclusive scan -> offsets (+ init cursors)
// ---------------------------------------------------------------------------
__global__ void scan_kernel() {
    __shared__ int ssum[1024];
    const int t = threadIdx.x;
    const int chunk = (N_NODES + 1023) / 1024;
    const int b = t * chunk;
    const int e = min(b + chunk, N_NODES);

    int s = 0;
    for (int i = b; i < e; i++) s += g_deg[i];
    ssum[t] = s;
    __syncthreads();
    for (int d = 1; d < 1024; d <<= 1) {
        int v = (t >= d) ? ssum[t - d] : 0;
        __syncthreads();
        ssum[t] += v;
        __syncthreads();
    }
    int run = ssum[t] - s;
    for (int i = b; i < e; i++) {
        g_off[i] = run;
        g_cur[i] = run;
        run += g_deg[i];
    }
    if (b < N_NODES && e == N_NODES) g_off[N_NODES] = run;
}

// ---------------------------------------------------------------------------
// Kernel 4: fill CSR edge lists
// ---------------------------------------------------------------------------
__global__ void fill_kernel(const int* __restrict__ src,
                            const int* __restrict__ dst, int n_edges) {
    int e = blockIdx.x * blockDim.x + threadIdx.x;
    if (e < n_edges) {
        int d = dst[e];
        int p = atomicAdd(&g_cur[d], 1);
        g_esrc[p] = src[e];
    }
}

// ---------------------------------------------------------------------------
// Kernel 5: per-node gather-aggregate -> bf16 hi/lo planes. One warp/node.
// ---------------------------------------------------------------------------
__device__ __forceinline__ void acc4(float4& a, float4 v) {
    a.x += v.x; a.y += v.y; a.z += v.z; a.w += v.w;
}
__device__ __forceinline__ void split4(float4 v, uint2& hi, uint2& lo) {
    __nv_bfloat16 h0 = __float2bfloat16(v.x);
    __nv_bfloat16 h1 = __float2bfloat16(v.y);
    __nv_bfloat16 h2 = __float2bfloat16(v.z);
    __nv_bfloat16 h3 = __float2bfloat16(v.w);
    __nv_bfloat16 l0 = __float2bfloat16(v.x - __bfloat162float(h0));
    __nv_bfloat16 l1 = __float2bfloat16(v.y - __bfloat162float(h1));
    __nv_bfloat16 l2 = __float2bfloat16(v.z - __bfloat162float(h2));
    __nv_bfloat16 l3 = __float2bfloat16(v.w - __bfloat162float(h3));
    __nv_bfloat162 hA = __nv_bfloat162(h0, h1), hB = __nv_bfloat162(h2, h3);
    __nv_bfloat162 lA = __nv_bfloat162(l0, l1), lB = __nv_bfloat162(l2, l3);
    hi.x = *reinterpret_cast<uint32_t*>(&hA); hi.y = *reinterpret_cast<uint32_t*>(&hB);
    lo.x = *reinterpret_cast<uint32_t*>(&lA); lo.y = *reinterpret_cast<uint32_t*>(&lB);
}

__global__ __launch_bounds__(256) void gather_kernel(const float* __restrict__ feature) {
    int node = (blockIdx.x * blockDim.x + threadIdx.x) >> 5;
    int lane = threadIdx.x & 31;
    if (node >= N_NODES) return;

    int beg = g_off[node];
    int end = g_off[node + 1];

    float4 acc0 = make_float4(0.f, 0.f, 0.f, 0.f);
    float4 acc1 = make_float4(0.f, 0.f, 0.f, 0.f);

    int i = beg;
    for (; i + 2 <= end; i += 2) {
        int s0 = g_esrc[i];
        int s1 = g_esrc[i + 1];
        const float4* f0 = reinterpret_cast<const float4*>(feature + (size_t)s0 * IN_DIM);
        const float4* f1 = reinterpret_cast<const float4*>(feature + (size_t)s1 * IN_DIM);
        float4 v00 = f0[lane];
        float4 v01 = f0[lane + 32];
        float4 v10 = f1[lane];
        float4 v11 = f1[lane + 32];
        acc4(acc0, v00); acc4(acc1, v01);
        acc4(acc0, v10); acc4(acc1, v11);
    }
    if (i < end) {
        int s0 = g_esrc[i];
        const float4* f0 = reinterpret_cast<const float4*>(feature + (size_t)s0 * IN_DIM);
        acc4(acc0, f0[lane]);
        acc4(acc1, f0[lane + 32]);
    }

    uint2 h0, l0, h1, l1;
    split4(acc0, h0, l0);
    split4(acc1, h1, l1);
    size_t base = (size_t)node * IN_DIM;
    *reinterpret_cast<uint2*>(g_hiA + base + 4 * lane)       = h0;
    *reinterpret_cast<uint2*>(g_hiA + base + 128 + 4 * lane) = h1;
    *reinterpret_cast<uint2*>(g_loA + base + 4 * lane)       = l0;
    *reinterpret_cast<uint2*>(g_loA + base + 128 + 4 * lane) = l1;
}

// ---------------------------------------------------------------------------
// Kernel 6: convert W -> transposed bf16 hi/lo planes  (B[n][k] = W[k][n])
// ---------------------------------------------------------------------------
__global__ void convw_kernel(const float* __restrict__ W) {
    int idx = blockIdx.x * blockDim.x + threadIdx.x;   // k*256 + n
    if (idx >= IN_DIM * OUT_DIM) return;
    int k = idx >> 8;
    int n = idx & 255;
    float w = W[idx];
    __nv_bfloat16 h = __float2bfloat16(w);
    __nv_bfloat16 l = __float2bfloat16(w - __bfloat162float(h));
    g_hiB[n * IN_DIM + k] = h;
    g_loB[n * IN_DIM + k] = l;
}

// ---------------------------------------------------------------------------
// Kernel 7: bf16 HMMA GEMM with cp.async 2-stage pipeline.
// CTA 128x128 tile, 8 warps (4M x 2N), 12 chunks of (plane-pass, K=64).
// Dynamic smem: 2 stages x (sA 16KB + sB 16KB) = 64KB.
// ---------------------------------------------------------------------------
#define SWX(o) ((o) ^ (((o) >> 3) & 0x70))
#define STAGE_BYTES 32768
#define GEMM_SMEM   (2 * STAGE_BYTES)

__global__ __launch_bounds__(256, 2) void gemm_mma_kernel(float* __restrict__ out) {
    extern __shared__ __align__(16) uint8_t smem[];

    const int tid  = threadIdx.x;
    const int lane = tid & 31;
    const int w    = tid >> 5;
    const int warpM = w & 3;          // 0..3
    const int warpN = w >> 2;         // 0..1
    const int m0 = blockIdx.x * 128;
    const int n0 = blockIdx.y * 128;

    const uint32_t sbase = smem_to_u32(smem);

    // per-thread tile-load coords (same for A and B): 4 x 16B each
    const int ldRow = tid >> 1;              // rows 0..127, 2 threads per row
    const int ldU0  = (tid & 1) * 4;         // u 0..3 or 4..7

    // ldmatrix per-lane address components
    const int aRow  = warpM * 32 + (lane & 15);
    const uint32_t aHalf = (uint32_t)((lane >> 4) << 4);         // 0 or 16
    const int bRowBase = warpN * 64 + (lane & 7) + (((lane >> 4) & 1) << 3);
    const uint32_t bHalf = (uint32_t)(((lane >> 3) & 1) << 4);   // 0 or 16

    float acc[2][8][4];
#pragma unroll
    for (int mi = 0; mi < 2; mi++)
#pragma unroll
        for (int nf = 0; nf < 8; nf++)
#pragma unroll
            for (int q = 0; q < 4; q++) acc[mi][nf][q] = 0.f;

    // prefetch helper: chunk 'it' into buffer it&1
    auto prefetch = [&](int it) {
        const int pass = it >> 2;
        const int k0   = (it & 3) * 64;
        const __nv_bfloat16* Ap = (pass < 2) ? g_hiA : g_loA;
        const __nv_bfloat16* Bp = (pass == 1) ? g_loB : g_hiB;
        const uint32_t sA = sbase + (uint32_t)((it & 1) * STAGE_BYTES);
        const uint32_t sB = sA + 16384;
#pragma unroll
        for (int l = 0; l < 4; ++l) {
            int u = ldU0 + ((l & 1) ? ((l & 2) ? 3 : 1) : ((l & 2) ? 2 : 0));
            // simpler: u = ldU0 + l (l in 0..3)
            u = ldU0 + l;
            cp16(sA + SWX(ldRow * 128 + u * 16),
                 Ap + (size_t)(m0 + ldRow) * IN_DIM + k0 + u * 8);
        }
#pragma unroll
        for (int l = 0; l < 4; ++l) {
            int u = ldU0 + l;
            cp16(sB + SWX(ldRow * 128 + u * 16),
                 Bp + (size_t)(n0 + ldRow) * IN_DIM + k0 + u * 8);
        }
        CP_COMMIT();
    };

    prefetch(0);

#pragma unroll 1
    for (int it = 0; it < 12; ++it) {
        if (it < 11) prefetch(it + 1);
        if (it < 11) { CP_WAIT(1); } else { CP_WAIT(0); }
        __syncthreads();

        const uint32_t sAu = sbase + (uint32_t)((it & 1) * STAGE_BYTES);
        const uint32_t sBu = sAu + 16384;

#pragma unroll
        for (int ks = 0; ks < 4; ++ks) {
            const uint32_t koff = (uint32_t)(ks * 32);
            uint32_t afr[2][4];
#pragma unroll
            for (int mi = 0; mi < 2; mi++) {
                const int r = aRow + mi * 16;
                uint32_t addr = sAu + (uint32_t)(r * 128)
                              + ((koff + aHalf) ^ ((uint32_t)((r << 4) & 0x70)));
                ldm4(afr[mi], addr);
            }
#pragma unroll
            for (int nf2 = 0; nf2 < 4; nf2++) {
                const int bRow = bRowBase + nf2 * 16;
                uint32_t baddr = sBu + (uint32_t)(bRow * 128)
                               + ((koff + bHalf) ^ ((uint32_t)((bRow << 4) & 0x70)));
                uint32_t bfr[4];
                ldm4(bfr, baddr);
#pragma unroll
                for (int mi = 0; mi < 2; mi++) {
                    mma16816(acc[mi][nf2 * 2],     afr[mi], bfr[0], bfr[1]);
                    mma16816(acc[mi][nf2 * 2 + 1], afr[mi], bfr[2], bfr[3]);
                }
            }
        }
        __syncthreads();
    }

    // --- epilogue ---
    const int groupID = lane >> 2;
    const int tig     = lane & 3;
#pragma unroll
    for (int mi = 0; mi < 2; mi++) {
#pragma unroll
        for (int nf = 0; nf < 8; nf++) {
            int row0 = m0 + warpM * 32 + mi * 16 + groupID;
            int col  = n0 + warpN * 64 + nf * 8 + tig * 2;
            if (row0 < N_NODES) {
                float2 v0 = make_float2(acc[mi][nf][0], acc[mi][nf][1]);
                *reinterpret_cast<float2*>(out + (size_t)row0 * OUT_DIM + col) = v0;
            }
            int row1 = row0 + 8;
            if (row1 < N_NODES) {
                float2 v1 = make_float2(acc[mi][nf][2], acc[mi][nf][3]);
                *reinterpret_cast<float2*>(out + (size_t)row1 * OUT_DIM + col) = v1;
            }
        }
    }
}

// ---------------------------------------------------------------------------
extern "C" void kernel_launch(void* const* d_in, const int* in_sizes, int n_in,
                              void* d_out, int out_size) {
    const float* feature = (const float*)d_in[0];
    const float* weight  = (const float*)d_in[1];
    const int*   src     = (const int*)d_in[2];
    const int*   dst     = (const int*)d_in[3];
    float*       out     = (float*)d_out;
    const int n_edges = in_sizes[2];

    zero_deg_kernel<<<(N_NODES + 255) / 256, 256>>>();
    hist_kernel<<<(n_edges + 255) / 256, 256>>>(dst, n_edges);
    scan_kernel<<<1, 1024>>>();
    fill_kernel<<<(n_edges + 255) / 256, 256>>>(src, dst, n_edges);
    convw_kernel<<<(IN_DIM * OUT_DIM + 255) / 256, 256>>>(weight);
    gather_kernel<<<(N_NODES + 7) / 8, 256>>>(feature);

    cudaFuncSetAttribute(gemm_mma_kernel,
                         cudaFuncAttributeMaxDynamicSharedMemorySize, GEMM_SMEM);
    dim3 grid(M_PAD / 128, OUT_DIM / 128);
    gemm_mma_kernel<<<grid, 256, GEMM_SMEM>>>(out);
}

// round 8
// speedup vs baseline: 1.4457x; 1.4457x over previous
#include <cuda_runtime.h>
#include <cuda_bf16.h>
#include <cstdint>

#define N_NODES 50000
#define N_EDGES_MAX 800000
#define IN_DIM  256
#define OUT_DIM 256
#define M_PAD   50176          // 392 * 128

// ---------------------------------------------------------------------------
// Device-global scratch (allocation-free).
// ---------------------------------------------------------------------------
__device__ int g_deg[N_NODES];
__device__ int g_off[N_NODES + 1];
__device__ int g_cur[N_NODES];
__device__ int g_esrc[N_EDGES_MAX];
#define SCAN_BLK 512
#define SCAN_NB  98            // 98*512 = 50176 >= N_NODES
__device__ int g_bsum[SCAN_NB];
__device__ int g_bpre[SCAN_NB];
__device__ unsigned g_tile_ctr;
// bf16 split planes of the aggregated features (A) and transposed weight (B)
// rows >= N_NODES are never written -> remain zero (device globals zero-init)
__device__ __align__(16) __nv_bfloat16 g_hiA[(size_t)M_PAD * IN_DIM];
__device__ __align__(16) __nv_bfloat16 g_loA[(size_t)M_PAD * IN_DIM];
__device__ __align__(16) __nv_bfloat16 g_hiB[(size_t)OUT_DIM * IN_DIM];  // [n][k]
__device__ __align__(16) __nv_bfloat16 g_loB[(size_t)OUT_DIM * IN_DIM];  // [n][k]

// ---------------------------------------------------------------------------
// helpers
// ---------------------------------------------------------------------------
__device__ __forceinline__ uint32_t smem_to_u32(const void* p) {
    uint32_t a;
    asm("{ .reg .u64 t; cvta.to.shared.u64 t, %1; cvt.u32.u64 %0, t; }"
        : "=r"(a) : "l"(p));
    return a;
}
__device__ __forceinline__ void ldm4(uint32_t* r, uint32_t addr) {
    asm volatile("ldmatrix.sync.aligned.m8n8.x4.shared.b16 {%0,%1,%2,%3}, [%4];"
                 : "=r"(r[0]), "=r"(r[1]), "=r"(r[2]), "=r"(r[3]) : "r"(addr));
}
__device__ __forceinline__ void mma16816(float* c, const uint32_t* a,
                                         uint32_t b0, uint32_t b1) {
    asm volatile(
        "mma.sync.aligned.m16n8k16.row.col.f32.bf16.bf16.f32 "
        "{%0,%1,%2,%3}, {%4,%5,%6,%7}, {%8,%9}, {%0,%1,%2,%3};"
        : "+f"(c[0]), "+f"(c[1]), "+f"(c[2]), "+f"(c[3])
        : "r"(a[0]), "r"(a[1]), "r"(a[2]), "r"(a[3]), "r"(b0), "r"(b1));
}

// ---------------------------------------------------------------------------
// Kernel 1: zero degree histogram
// ---------------------------------------------------------------------------
__global__ void zero_deg_kernel() {
    int i = blockIdx.x * blockDim.x + threadIdx.x;
    if (i < N_NODES) g_deg[i] = 0;
}

// ---------------------------------------------------------------------------
// Kernel 2: degree histogram over dst
// ---------------------------------------------------------------------------
__global__ void hist_kernel(const int* __restrict__ dst, int n_edges) {
    int e = blockIdx.x * blockDim.x + threadIdx.x;
    if (e < n_edges) atomicAdd(&g_deg[dst[e]], 1);
}

// ---------------------------------------------------------------------------
// Kernels 3a/3b/3c: parallel exclusive scan of degrees -> offsets + cursors
// ---------------------------------------------------------------------------
__global__ __launch_bounds__(SCAN_BLK) void scan_a_kernel() {
    __shared__ int sh[SCAN_BLK];
    int t = threadIdx.x;
    int i = blockIdx.x * SCAN_BLK + t;
    sh[t] = (i < N_NODES) ? g_deg[i] : 0;
    __syncthreads();
    for (int s = SCAN_BLK / 2; s > 0; s >>= 1) {
        if (t < s) sh[t] += sh[t + s];
        __syncthreads();
    }
    if (t == 0) g_bsum[blockIdx.x] = sh[0];
}

__global__ void scan_b_kernel() {      // 1 block, 128 threads
    __shared__ int sh[128];
    int t = threadIdx.x;
    int v = (t < SCAN_NB) ? g_bsum[t] : 0;
    sh[t] = v;
    __syncthreads();
    for (int d = 1; d < 128; d <<= 1) {
        int x = (t >= d) ? sh[t - d] : 0;
        __syncthreads();
        sh[t] += x;
        __syncthreads();
    }
    if (t < SCAN_NB) g_bpre[t] = sh[t] - v;   // exclusive block prefix
}

__global__ __launch_bounds__(SCAN_BLK) void scan_c_kernel() {
    __shared__ int sh[SCAN_BLK];
    int t = threadIdx.x;
    int i = blockIdx.x * SCAN_BLK + t;
    int v = (i < N_NODES) ? g_deg[i] : 0;
    sh[t] = v;
    __syncthreads();
    for (int d = 1; d < SCAN_BLK; d <<= 1) {
        int x = (t >= d) ? sh[t - d] : 0;
        __syncthreads();
        sh[t] += x;
        __syncthreads();
    }
    int off = g_bpre[blockIdx.x] + sh[t] - v;  // exclusive global prefix
    if (i < N_NODES) {
        g_off[i] = off;
        g_cur[i] = off;
    }
    if (i == N_NODES - 1) g_off[N_NODES] = off + v;
}

// ---------------------------------------------------------------------------
// Kernel 4: fill CSR edge lists
// ---------------------------------------------------------------------------
__global__ void fill_kernel(const int* __restrict__ src,
                            const int* __restrict__ dst, int n_edges) {
    int e = blockIdx.x * blockDim.x + threadIdx.x;
    if (e < n_edges) {
        int d = dst[e];
        int p = atomicAdd(&g_cur[d], 1);
        g_esrc[p] = src[e];
    }
}

// ---------------------------------------------------------------------------
// Kernel 5: gather v2 -> bf16 hi/lo planes. TWO warps per node (half row
// each), 1 float4 per lane per edge, 4-edge unroll for MLP.
// ---------------------------------------------------------------------------
__device__ __forceinline__ void acc4(float4& a, float4 v) {
    a.x += v.x; a.y += v.y; a.z += v.z; a.w += v.w;
}
__device__ __forceinline__ void split4(float4 v, uint2& hi, uint2& lo) {
    __nv_bfloat16 h0 = __float2bfloat16(v.x);
    __nv_bfloat16 h1 = __float2bfloat16(v.y);
    __nv_bfloat16 h2 = __float2bfloat16(v.z);
    __nv_bfloat16 h3 = __float2bfloat16(v.w);
    __nv_bfloat16 l0 = __float2bfloat16(v.x - __bfloat162float(h0));
    __nv_bfloat16 l1 = __float2bfloat16(v.y - __bfloat162float(h1));
    __nv_bfloat16 l2 = __float2bfloat16(v.z - __bfloat162float(h2));
    __nv_bfloat16 l3 = __float2bfloat16(v.w - __bfloat162float(h3));
    __nv_bfloat162 hA = __nv_bfloat162(h0, h1), hB = __nv_bfloat162(h2, h3);
    __nv_bfloat162 lA = __nv_bfloat162(l0, l1), lB = __nv_bfloat162(l2, l3);
    hi.x = *reinterpret_cast<uint32_t*>(&hA); hi.y = *reinterpret_cast<uint32_t*>(&hB);
    lo.x = *reinterpret_cast<uint32_t*>(&lA); lo.y = *reinterpret_cast<uint32_t*>(&lB);
}

__global__ __launch_bounds__(256) void gather_kernel(const float* __restrict__ feature) {
    int gw   = (blockIdx.x * blockDim.x + threadIdx.x) >> 5;
    int node = gw >> 1;
    int half = gw & 1;
    int lane = threadIdx.x & 31;
    if (node >= N_NODES) return;

    int beg = g_off[node];
    int end = g_off[node + 1];

    const float4* fbase = reinterpret_cast<const float4*>(feature) + half * 32 + lane;

    float4 acc = make_float4(0.f, 0.f, 0.f, 0.f);
    int i = beg;
    for (; i + 4 <= end; i += 4) {
        int s0 = g_esrc[i];
        int s1 = g_esrc[i + 1];
        int s2 = g_esrc[i + 2];
        int s3 = g_esrc[i + 3];
        float4 v0 = fbase[(size_t)s0 * 64];
        float4 v1 = fbase[(size_t)s1 * 64];
        float4 v2 = fbase[(size_t)s2 * 64];
        float4 v3 = fbase[(size_t)s3 * 64];
        acc4(acc, v0); acc4(acc, v1); acc4(acc, v2); acc4(acc, v3);
    }
    for (; i < end; ++i) {
        acc4(acc, fbase[(size_t)g_esrc[i] * 64]);
    }

    uint2 h, l;
    split4(acc, h, l);
    size_t base = (size_t)node * IN_DIM + half * 128;
    *reinterpret_cast<uint2*>(g_hiA + base + 4 * lane) = h;
    *reinterpret_cast<uint2*>(g_loA + base + 4 * lane) = l;
}

// ---------------------------------------------------------------------------
// Kernel 6: convert W -> transposed bf16 hi/lo planes  (B[n][k] = W[k][n])
// Also resets the GEMM tile ticket for this replay.
// ---------------------------------------------------------------------------
__global__ void convw_kernel(const float* __restrict__ W) {
    int idx = blockIdx.x * blockDim.x + threadIdx.x;   // k*256 + n
    if (idx == 0) g_tile_ctr = 0;
    if (idx >= IN_DIM * OUT_DIM) return;
    int k = idx >> 8;
    int n = idx & 255;
    float w = W[idx];
    __nv_bfloat16 h = __float2bfloat16(w);
    __nv_bfloat16 l = __float2bfloat16(w - __bfloat162float(h));
    g_hiB[n * IN_DIM + k] = h;
    g_loB[n * IN_DIM + k] = l;
}

// ---------------------------------------------------------------------------
// Kernel 7: bf16 HMMA GEMM, 3 error-compensated passes, persistent CTAs with
// dynamic tile ticket. Tile 128x128, 8 warps (4M x 2N), K-chunk 64.
// ---------------------------------------------------------------------------
#define SWX(o) ((o) ^ (((o) >> 3) & 0x70))
#define NTILES (2 * (M_PAD / 128))   // 784

__global__ __launch_bounds__(256, 2) void gemm_mma_kernel(float* __restrict__ out) {
    __shared__ __align__(16) uint8_t sA[128 * 128];
    __shared__ __align__(16) uint8_t sB[128 * 128];
    __shared__ unsigned s_tile;

    const int tid  = threadIdx.x;
    const int lane = tid & 31;
    const int w    = tid >> 5;
    const int warpM = w & 3;
    const int warpN = w >> 2;

    const uint32_t sAu = smem_to_u32(sA);
    const uint32_t sBu = smem_to_u32(sB);

    const int aRow  = warpM * 32 + (lane & 15);
    const uint32_t aHalf = (uint32_t)((lane >> 4) << 4);
    const int bRowBase = warpN * 64 + (lane & 7) + (((lane >> 4) & 1) << 3);
    const uint32_t bHalf = (uint32_t)(((lane >> 3) & 1) << 4);
    const int groupID = lane >> 2;
    const int tig     = lane & 3;

    for (;;) {
        __syncthreads();
        if (tid == 0) s_tile = atomicAdd(&g_tile_ctr, 1u);
        __syncthreads();
        const unsigned t = s_tile;
        if (t >= NTILES) break;
        const int m0 = (int)(t >> 1) * 128;
        const int n0 = (int)(t & 1) * 128;

        float acc[2][8][4];
#pragma unroll
        for (int mi = 0; mi < 2; mi++)
#pragma unroll
            for (int nf = 0; nf < 8; nf++)
#pragma unroll
                for (int q = 0; q < 4; q++) acc[mi][nf][q] = 0.f;

#pragma unroll 1
        for (int it = 0; it < 12; ++it) {
            const int pass = it >> 2;
            const int k0   = (it & 3) * 64;
            const __nv_bfloat16* Ap = (pass < 2) ? g_hiA : g_loA;
            const __nv_bfloat16* Bp = (pass == 1) ? g_loB : g_hiB;

#pragma unroll
            for (int l = 0; l < 4; ++l) {
                int idx = tid + 256 * l;
                int row = idx >> 3;
                int u   = idx & 7;
                uint4 v = *reinterpret_cast<const uint4*>(
                              Ap + (size_t)(m0 + row) * IN_DIM + k0 + u * 8);
                *reinterpret_cast<uint4*>(sA + SWX(row * 128 + u * 16)) = v;
            }
#pragma unroll
            for (int l = 0; l < 4; ++l) {
                int idx = tid + 256 * l;
                int row = idx >> 3;
                int u   = idx & 7;
                uint4 v = *reinterpret_cast<const uint4*>(
                              Bp + (size_t)(n0 + row) * IN_DIM + k0 + u * 8);
                *reinterpret_cast<uint4*>(sB + SWX(row * 128 + u * 16)) = v;
            }
            __syncthreads();

#pragma unroll
            for (int ks = 0; ks < 4; ++ks) {
                const uint32_t koff = (uint32_t)(ks * 32);
                uint32_t afr[2][4];
#pragma unroll
                for (int mi = 0; mi < 2; mi++) {
                    const int r = aRow + mi * 16;
                    uint32_t addr = sAu + (uint32_t)(r * 128)
                                  + ((koff + aHalf) ^ ((uint32_t)((r << 4) & 0x70)));
                    ldm4(afr[mi], addr);
                }
#pragma unroll
                for (int nf2 = 0; nf2 < 4; nf2++) {
                    const int bRow = bRowBase + nf2 * 16;
                    uint32_t baddr = sBu + (uint32_t)(bRow * 128)
                                   + ((koff + bHalf) ^ ((uint32_t)((bRow << 4) & 0x70)));
                    uint32_t bfr[4];
                    ldm4(bfr, baddr);
#pragma unroll
                    for (int mi = 0; mi < 2; mi++) {
                        mma16816(acc[mi][nf2 * 2],     afr[mi], bfr[0], bfr[1]);
                        mma16816(acc[mi][nf2 * 2 + 1], afr[mi], bfr[2], bfr[3]);
                    }
                }
            }
            __syncthreads();
        }

        // epilogue
#pragma unroll
        for (int mi = 0; mi < 2; mi++) {
#pragma unroll
            for (int nf = 0; nf < 8; nf++) {
                int row0 = m0 + warpM * 32 + mi * 16 + groupID;
                int col  = n0 + warpN * 64 + nf * 8 + tig * 2;
                if (row0 < N_NODES) {
                    float2 v0 = make_float2(acc[mi][nf][0], acc[mi][nf][1]);
                    *reinterpret_cast<float2*>(out + (size_t)row0 * OUT_DIM + col) = v0;
                }
                int row1 = row0 + 8;
                if (row1 < N_NODES) {
                    float2 v1 = make_float2(acc[mi][nf][2], acc[mi][nf][3]);
                    *reinterpret_cast<float2*>(out + (size_t)row1 * OUT_DIM + col) = v1;
                }
            }
        }
    }
}

// ---------------------------------------------------------------------------
extern "C" void kernel_launch(void* const* d_in, const int* in_sizes, int n_in,
                              void* d_out, int out_size) {
    const float* feature = (const float*)d_in[0];
    const float* weight  = (const float*)d_in[1];
    const int*   src     = (const int*)d_in[2];
    const int*   dst     = (const int*)d_in[3];
    float*       out     = (float*)d_out;
    const int n_edges = in_sizes[2];

    zero_deg_kernel<<<(N_NODES + 255) / 256, 256>>>();
    hist_kernel<<<(n_edges + 255) / 256, 256>>>(dst, n_edges);
    scan_a_kernel<<<SCAN_NB, SCAN_BLK>>>();
    scan_b_kernel<<<1, 128>>>();
    scan_c_kernel<<<SCAN_NB, SCAN_BLK>>>();
    fill_kernel<<<(n_edges + 255) / 256, 256>>>(src, dst, n_edges);
    convw_kernel<<<(IN_DIM * OUT_DIM + 255) / 256, 256>>>(weight);
    // gather: 2 warps per node
    {
        int warps = 2 * N_NODES;
        int blocks = (warps * 32 + 255) / 256;
        gather_kernel<<<blocks, 256>>>(feature);
    }
    gemm_mma_kernel<<<296, 256>>>(out);
}